// round 6
// baseline (speedup 1.0000x reference)
#include <cuda_runtime.h>

#define N_NODES 10000
#define KK1 10
#define KK2 25
#define DIM 64
#define OUTD 128
#define NGRAPH 64
#define NSLOT 2

typedef unsigned long long ull;

__device__ float g_Seg[NGRAPH * OUTD];

__device__ __forceinline__ void ffma2(ull& acc, ull a, ull b) {
    asm("fma.rn.f32x2 %0, %1, %2, %0;" : "+l"(acc) : "l"(a), "l"(b));
}
__device__ __forceinline__ float f2sum(ull v) {
    return __uint_as_float((unsigned)v) + __uint_as_float((unsigned)(v >> 32));
}
__device__ __forceinline__ unsigned smem_u32(const void* p) {
    unsigned a;
    asm("{ .reg .u64 t; cvta.to.shared.u64 t, %1; cvt.u32.u64 %0, t; }"
        : "=r"(a) : "l"(p));
    return a;
}
__device__ __forceinline__ void mbar_init(unsigned addr, unsigned cnt) {
    asm volatile("mbarrier.init.shared.b64 [%0], %1;" :: "r"(addr), "r"(cnt) : "memory");
}
__device__ __forceinline__ void mbar_arrive(unsigned addr) {
    asm volatile("mbarrier.arrive.release.cta.shared::cta.b64 _, [%0];" :: "r"(addr) : "memory");
}
__device__ __forceinline__ void mbar_wait(unsigned addr, int phase) {
    asm volatile(
        "{\n\t.reg .pred P;\n\t"
        "WL_%=:\n\t"
        "mbarrier.try_wait.parity.acquire.cta.shared::cta.b64 P, [%0], %1, 0x989680;\n\t"
        "@P bra.uni WD_%=;\n\t"
        "bra.uni WL_%=;\n\t"
        "WD_%=:\n\t}"
        :: "r"(addr), "r"(phase) : "memory");
}

#define W0T_LD 132              // 33 float4/row -> conflict-free LDS.128
#define W1T_LD 260              // 65 float4/row -> conflict-free LDS.128
#define XS_NODE 1408            // 11 * 128
#define XS_PAIR 2816

// smem float offsets
#define OFF_W0T  8
#define OFF_B0   (OFF_W0T + 128 * W0T_LD)      // 16904
#define OFF_B1   (OFF_B0 + 128)                // 17032
#define OFF_W1T  (OFF_B1 + 128)                // 17160
#define OFF_RING (OFF_W1T + 128 * W1T_LD)      // 50440
#define OFF_XR   (OFF_RING + NSLOT * XS_PAIR)  // 56072
#define SM_FLOATS (OFF_XR + 2 * 512)           // 57096 -> 228,384 B

// ---------------------------------------------------------------------------
// kZ: zero segment accumulator (kA consumers atomicAdd into it).
// ---------------------------------------------------------------------------
extern "C" __global__ void kZ() {
    g_Seg[blockIdx.x * 512 + threadIdx.x] = 0.f;
}

// ---------------------------------------------------------------------------
// Kernel A (fully fused): warp-specialized, 512 threads, 1 block/SM.
//   warps 0-3  (t<128) : consumers. GEMM1 (X@w0, 2 cols/thread) ->
//                        XR staged in smem -> GEMM2 (XR@w1) -> relu ->
//                        atomicAdd into g_Seg.
//   warps 4-15 (t>=128): producers, exactly 1 streaming task per thread
//                        (26 independent LDG.128 -> max MLP).
// 2-slot pair ring + double-buffered XR, mbarrier handoff.
// ---------------------------------------------------------------------------
extern "C" __global__ void __launch_bounds__(512, 1)
kA(const float* __restrict__ h0, const float* __restrict__ h1,
   const float* __restrict__ h2, const float* __restrict__ w0,
   const float* __restrict__ b0, const float* __restrict__ w1,
   const float* __restrict__ b1, const int* __restrict__ gid)
{
    extern __shared__ float sm[];
    float* w0Ts = sm + OFF_W0T;
    float* b0s  = sm + OFF_B0;
    float* b1s  = sm + OFF_B1;
    float* w1Ts = sm + OFF_W1T;
    float* ring = sm + OFF_RING;
    float* XRs  = sm + OFF_XR;

    const int t = threadIdx.x;
    const unsigned mb = smem_u32(sm);

    if (t == 0) {
        #pragma unroll
        for (int s = 0; s < NSLOT; ++s) {
            mbar_init(mb + s * 16, 384);       // full: 384 producer arrivals
            mbar_init(mb + s * 16 + 8, 128);   // empty: 128 consumer arrivals
        }
    }

    // Stage w0 transposed: w0Ts[col][k] = w0[k][col].
    for (int i = t; i < 4096; i += 512) {
        const int k  = i >> 5;
        const int cq = i & 31;
        const float4 v = __ldg((const float4*)(w0 + k * 128) + cq);
        w0Ts[(cq * 4 + 0) * W0T_LD + k] = v.x;
        w0Ts[(cq * 4 + 1) * W0T_LD + k] = v.y;
        w0Ts[(cq * 4 + 2) * W0T_LD + k] = v.z;
        w0Ts[(cq * 4 + 3) * W0T_LD + k] = v.w;
    }
    // Stage w1 transposed: w1Ts[col][k] = w1[k][col]; w1 is [256][128].
    for (int i = t; i < 8192; i += 512) {
        const int k  = i >> 5;
        const int cq = i & 31;
        const float4 v = __ldg((const float4*)(w1 + k * 128) + cq);
        w1Ts[(cq * 4 + 0) * W1T_LD + k] = v.x;
        w1Ts[(cq * 4 + 1) * W1T_LD + k] = v.y;
        w1Ts[(cq * 4 + 2) * W1T_LD + k] = v.z;
        w1Ts[(cq * 4 + 3) * W1T_LD + k] = v.w;
    }
    if (t < 128) { b0s[t] = b0[t]; b1s[t] = b1[t]; }
    __syncthreads();

    if (t >= 128) {
        // ===================== PRODUCER (1 task/thread) =====================
        const int task = t - 128;               // 0..383
        int slot = 0, ph = 1;                   // empty passes immediately rnd 1
        for (int np = blockIdx.x * 2; np < N_NODES; np += gridDim.x * 2) {
            mbar_wait(mb + slot * 16 + 8, ph);
            float* Xb = ring + slot * XS_PAIR;

            if (task < 320) {
                const int node = task / 160;
                const int rem  = task - node * 160;
                const int j    = rem >> 4;
                const int c4   = rem & 15;
                const int base = (np + node) * KK1 + j;
                const float4* q = (const float4*)(h2 + base * (KK2 * DIM)) + c4;
                float4 s0 = make_float4(0.f, 0.f, 0.f, 0.f);
                float4 s1 = make_float4(0.f, 0.f, 0.f, 0.f);
                #pragma unroll
                for (int k = 0; k < 24; k += 2) {
                    const float4 a = __ldg(q + k * 16);
                    const float4 b = __ldg(q + (k + 1) * 16);
                    s0.x += a.x; s0.y += a.y; s0.z += a.z; s0.w += a.w;
                    s1.x += b.x; s1.y += b.y; s1.z += b.z; s1.w += b.w;
                }
                const float4 a = __ldg(q + 24 * 16);
                s0.x += a.x; s0.y += a.y; s0.z += a.z; s0.w += a.w;
                float4* xrow = (float4*)(Xb + node * XS_NODE + j * 128);
                xrow[16 + c4] = make_float4((s0.x + s1.x) * 0.04f,
                                            (s0.y + s1.y) * 0.04f,
                                            (s0.z + s1.z) * 0.04f,
                                            (s0.w + s1.w) * 0.04f);
                xrow[c4] = __ldg((const float4*)(h1 + base * DIM) + c4);
            } else if (task < 352) {
                const int idx = task - 320;
                const int node = idx >> 4, c4 = idx & 15;
                ((float4*)(Xb + node * XS_NODE + 10 * 128))[c4] =
                    __ldg((const float4*)(h0 + (np + node) * DIM) + c4);
            } else {
                const int idx = task - 352;
                const int node = idx >> 4, c4 = idx & 15;
                const float4* q = (const float4*)(h1 + (np + node) * KK1 * DIM) + c4;
                float4 s = make_float4(0.f, 0.f, 0.f, 0.f);
                #pragma unroll
                for (int j = 0; j < KK1; ++j) {
                    const float4 v = __ldg(q + j * 16);
                    s.x += v.x; s.y += v.y; s.z += v.z; s.w += v.w;
                }
                ((float4*)(Xb + node * XS_NODE + 10 * 128))[16 + c4] =
                    make_float4(s.x * 0.1f, s.y * 0.1f, s.z * 0.1f, s.w * 0.1f);
            }
            mbar_arrive(mb + slot * 16);            // full
            if (++slot == NSLOT) { slot = 0; ph ^= 1; }
        }
    } else {
        // ===================== CONSUMER =====================
        const int node = t >> 6;                   // 0 or 1
        const int col  = t & 63;                   // owns col and col+64
        const ulonglong2* wpa = (const ulonglong2*)(w0Ts + col * W0T_LD);
        const ulonglong2* wpb = (const ulonglong2*)(w0Ts + (col + 64) * W0T_LD);
        const ulonglong2* vpa = (const ulonglong2*)(w1Ts + col * W1T_LD);
        const ulonglong2* vpb = (const ulonglong2*)(w1Ts + (col + 64) * W1T_LD);
        const float bbA = b0s[col];
        const float bbB = b0s[col + 64];
        const float cbA = b1s[col];
        const float cbB = b1s[col + 64];

        int slot = 0, ph = 0;
        for (int np = blockIdx.x * 2; np < N_NODES; np += gridDim.x * 2) {
            mbar_wait(mb + slot * 16, ph);          // full
            const float* X = ring + slot * XS_PAIR + node * XS_NODE;

            // --- GEMM1: Y = relu(X @ w0 + b0), 2 cols ---
            ull accA[11], accB[11];
            #pragma unroll
            for (int r = 0; r < 11; ++r) { accA[r] = 0ull; accB[r] = 0ull; }

            #pragma unroll 2
            for (int kq = 0; kq < 32; ++kq) {
                const ulonglong2 wa = wpa[kq];
                const ulonglong2 wb = wpb[kq];
                #pragma unroll
                for (int r = 0; r < 11; ++r) {
                    const ulonglong2 x = *(const ulonglong2*)(X + r * 128 + kq * 4);
                    ffma2(accA[r], x.x, wa.x);
                    ffma2(accA[r], x.y, wa.y);
                    ffma2(accB[r], x.x, wb.x);
                    ffma2(accB[r], x.y, wb.y);
                }
            }

            float ymA = 0.f, ymB = 0.f;
            #pragma unroll
            for (int r = 0; r < KK1; ++r) {
                ymA += fmaxf(f2sum(accA[r]) + bbA, 0.f);
                ymB += fmaxf(f2sum(accB[r]) + bbB, 0.f);
            }
            const float a01A = fmaxf(f2sum(accA[10]) + bbA, 0.f);
            const float a01B = fmaxf(f2sum(accB[10]) + bbB, 0.f);

            // --- stage XR row in smem (double-buffered by slot) ---
            float* xr = XRs + slot * 512 + node * 256;
            xr[col]            = a01A;
            xr[col + 64]       = a01B;
            xr[128 + col]      = ymA * 0.1f;
            xr[128 + col + 64] = ymB * 0.1f;
            asm volatile("bar.sync 1, 128;" ::: "memory");

            // --- GEMM2: out = relu(XR @ w1 + b1), 2 cols -> seg atomics ---
            ull s0 = 0ull, s1 = 0ull;
            const ulonglong2* xq = (const ulonglong2*)xr;
            #pragma unroll 4
            for (int kq = 0; kq < 64; ++kq) {
                const ulonglong2 x = xq[kq];
                const ulonglong2 va = vpa[kq];
                const ulonglong2 vb = vpb[kq];
                ffma2(s0, x.x, va.x); ffma2(s0, x.y, va.y);
                ffma2(s1, x.x, vb.x); ffma2(s1, x.y, vb.y);
            }
            const float o0 = fmaxf(f2sum(s0) + cbA, 0.f);
            const float o1 = fmaxf(f2sum(s1) + cbB, 0.f);

            float* seg = g_Seg + __ldg(gid + np + node) * OUTD;
            atomicAdd(seg + col,      o0);
            atomicAdd(seg + col + 64, o1);

            mbar_arrive(mb + slot * 16 + 8);        // empty
            if (++slot == NSLOT) { slot = 0; ph ^= 1; }
        }
    }
}

// ---------------------------------------------------------------------------
// Kernel C: readout MLP, one block per graph.
// ---------------------------------------------------------------------------
extern "C" __global__ void __launch_bounds__(64, 8)
kC(const float* __restrict__ wr1, const float* __restrict__ br1,
   const float* __restrict__ wr2, const float* __restrict__ br2,
   const float* __restrict__ wr3, const float* __restrict__ br3,
   float* __restrict__ out)
{
    __shared__ float r1s[35];
    __shared__ float r2s[35];
    const int g = blockIdx.x, t = threadIdx.x;
    const float SC = 1.0507009873554805f;
    const float AL = 1.6732632423543772f;

    if (t < 35) {
        float acc = br1[t];
        #pragma unroll 4
        for (int k = 0; k < OUTD; ++k)
            acc = fmaf(g_Seg[g * OUTD + k], wr1[k * 35 + t], acc);
        r1s[t] = (acc > 0.f) ? SC * acc : SC * AL * (expf(acc) - 1.f);
    }
    __syncthreads();

    if (t < 35) {
        float acc = br2[t];
        #pragma unroll
        for (int k = 0; k < 35; ++k)
            acc = fmaf(r1s[k], wr2[k * 35 + t], acc);
        r2s[t] = (acc > 0.f) ? SC * acc : SC * AL * (expf(acc) - 1.f);
    }
    __syncthreads();

    if (t == 0) {
        float acc = br3[0];
        #pragma unroll
        for (int k = 0; k < 35; ++k)
            acc = fmaf(r2s[k], wr3[k], acc);
        out[g] = acc;
    }
}

// ---------------------------------------------------------------------------
extern "C" void kernel_launch(void* const* d_in, const int* in_sizes, int n_in,
                              void* d_out, int out_size)
{
    const float* h0  = (const float*)d_in[0];
    const float* h1  = (const float*)d_in[1];
    const float* h2  = (const float*)d_in[2];
    const float* w0  = (const float*)d_in[3];
    const float* b0  = (const float*)d_in[4];
    const float* w1  = (const float*)d_in[5];
    const float* b1  = (const float*)d_in[6];
    const float* wr1 = (const float*)d_in[7];
    const float* br1 = (const float*)d_in[8];
    const float* wr2 = (const float*)d_in[9];
    const float* br2 = (const float*)d_in[10];
    const float* wr3 = (const float*)d_in[11];
    const float* br3 = (const float*)d_in[12];
    const int*   gid = (const int*)d_in[13];

    const int smA = SM_FLOATS * 4;   // 228,384 B
    cudaFuncSetAttribute(kA, cudaFuncAttributeMaxDynamicSharedMemorySize, smA);

    kZ<<<16, 512>>>();
    kA<<<148, 512, smA>>>(h0, h1, h2, w0, b0, w1, b1, gid);
    kC<<<NGRAPH, 64>>>(wr1, br1, wr2, br2, wr3, br3, (float*)d_out);
}

// round 7
// speedup vs baseline: 1.3621x; 1.3621x over previous
#include <cuda_runtime.h>

#define N_NODES 10000
#define KK1 10
#define KK2 25
#define DIM 64
#define OUTD 128
#define NGRAPH 64
#define NSLOT 4

typedef unsigned long long ull;

__device__ float g_XR[N_NODES * 256];   // per node0: [a01(128) | mean_relu_a12(128)]
__device__ float g_Seg[NGRAPH * OUTD];

__device__ __forceinline__ void ffma2(ull& acc, ull a, ull b) {
    asm("fma.rn.f32x2 %0, %1, %2, %0;" : "+l"(acc) : "l"(a), "l"(b));
}
__device__ __forceinline__ float f2sum(ull v) {
    return __uint_as_float((unsigned)v) + __uint_as_float((unsigned)(v >> 32));
}
__device__ __forceinline__ unsigned smem_u32(const void* p) {
    unsigned a;
    asm("{ .reg .u64 t; cvta.to.shared.u64 t, %1; cvt.u32.u64 %0, t; }"
        : "=r"(a) : "l"(p));
    return a;
}
__device__ __forceinline__ void mbar_init(unsigned addr, unsigned cnt) {
    asm volatile("mbarrier.init.shared.b64 [%0], %1;" :: "r"(addr), "r"(cnt) : "memory");
}
__device__ __forceinline__ void mbar_arrive(unsigned addr) {
    asm volatile("mbarrier.arrive.release.cta.shared::cta.b64 _, [%0];" :: "r"(addr) : "memory");
}
__device__ __forceinline__ void mbar_wait(unsigned addr, int phase) {
    asm volatile(
        "{\n\t.reg .pred P;\n\t"
        "WL_%=:\n\t"
        "mbarrier.try_wait.parity.acquire.cta.shared::cta.b64 P, [%0], %1, 0x989680;\n\t"
        "@P bra.uni WD_%=;\n\t"
        "bra.uni WL_%=;\n\t"
        "WD_%=:\n\t}"
        :: "r"(addr), "r"(phase) : "memory");
}

#define W0T_LD 132              // 33 float4/row -> conflict-free LDS.128
#define XS_NODE 1408            // 11 * 128
#define XS_PAIR 2816

// ---------------------------------------------------------------------------
// Kernel A: UNCHANGED from R5 (proven 139.9us). Warp-specialized, 384 thr:
//   warps 0-3  (t<128): GEMM consumers, 2 columns per thread.
//   warps 4-11 (t>=128): streaming producers. 4-slot ring, 1 block/SM.
// Also zeroes g_Seg in its prologue (kB consumes it afterwards).
// ---------------------------------------------------------------------------
extern "C" __global__ void __launch_bounds__(384, 1)
kA(const float* __restrict__ h0, const float* __restrict__ h1,
   const float* __restrict__ h2, const float* __restrict__ w0,
   const float* __restrict__ b0)
{
    extern __shared__ float sm[];
    float* w0Ts = sm + 8;                  // [128 cols][132]
    float* b0s  = w0Ts + 16896;            // 128
    float* ring = b0s + 128;               // NSLOT * 2816

    const int t = threadIdx.x;
    const unsigned mb = smem_u32(sm);

    if (t == 0) {
        #pragma unroll
        for (int s = 0; s < NSLOT; ++s) {
            mbar_init(mb + s * 16, 256);       // full: 256 producer arrivals
            mbar_init(mb + s * 16 + 8, 128);   // empty: 128 consumer arrivals
        }
    }

    // Zero segment accumulator (kB runs after kA in stream order).
    if (blockIdx.x < 22) {
        const int idx = blockIdx.x * 384 + t;
        if (idx < NGRAPH * OUTD) g_Seg[idx] = 0.f;
    }

    // Stage w0 transposed: w0Ts[col][k] = w0[k][col].
    for (int i = t; i < 4096; i += 384) {
        const int k  = i >> 5;
        const int cq = i & 31;
        const float4 v = __ldg((const float4*)(w0 + k * 128) + cq);
        w0Ts[(cq * 4 + 0) * W0T_LD + k] = v.x;
        w0Ts[(cq * 4 + 1) * W0T_LD + k] = v.y;
        w0Ts[(cq * 4 + 2) * W0T_LD + k] = v.z;
        w0Ts[(cq * 4 + 3) * W0T_LD + k] = v.w;
    }
    if (t < 128) b0s[t] = b0[t];
    __syncthreads();

    if (t >= 128) {
        // ===================== PRODUCER =====================
        const int p = t - 128;               // 0..255
        int slot = 0, ph = 1;
        for (int np = blockIdx.x * 2; np < N_NODES; np += gridDim.x * 2) {
            mbar_wait(mb + slot * 16 + 8, ph);
            float* Xb = ring + slot * XS_PAIR;

            #pragma unroll
            for (int pass = 0; pass < 2; ++pass) {
                const int task = p + pass * 256;
                if (task < 320) {
                    const int node = task / 160;
                    const int rem  = task - node * 160;
                    const int j    = rem >> 4;
                    const int c4   = rem & 15;
                    const int base = (np + node) * KK1 + j;
                    const float4* q = (const float4*)(h2 + base * (KK2 * DIM)) + c4;
                    float4 s0 = make_float4(0.f, 0.f, 0.f, 0.f);
                    float4 s1 = make_float4(0.f, 0.f, 0.f, 0.f);
                    #pragma unroll
                    for (int k = 0; k < 24; k += 2) {
                        const float4 a = __ldg(q + k * 16);
                        const float4 b = __ldg(q + (k + 1) * 16);
                        s0.x += a.x; s0.y += a.y; s0.z += a.z; s0.w += a.w;
                        s1.x += b.x; s1.y += b.y; s1.z += b.z; s1.w += b.w;
                    }
                    const float4 a = __ldg(q + 24 * 16);
                    s0.x += a.x; s0.y += a.y; s0.z += a.z; s0.w += a.w;
                    float4* xrow = (float4*)(Xb + node * XS_NODE + j * 128);
                    xrow[16 + c4] = make_float4((s0.x + s1.x) * 0.04f,
                                                (s0.y + s1.y) * 0.04f,
                                                (s0.z + s1.z) * 0.04f,
                                                (s0.w + s1.w) * 0.04f);
                    xrow[c4] = __ldg((const float4*)(h1 + base * DIM) + c4);
                } else if (task < 352) {
                    const int idx = task - 320;
                    const int node = idx >> 4, c4 = idx & 15;
                    ((float4*)(Xb + node * XS_NODE + 10 * 128))[c4] =
                        __ldg((const float4*)(h0 + (np + node) * DIM) + c4);
                } else if (task < 384) {
                    const int idx = task - 352;
                    const int node = idx >> 4, c4 = idx & 15;
                    const float4* q = (const float4*)(h1 + (np + node) * KK1 * DIM) + c4;
                    float4 s = make_float4(0.f, 0.f, 0.f, 0.f);
                    #pragma unroll
                    for (int j = 0; j < KK1; ++j) {
                        const float4 v = __ldg(q + j * 16);
                        s.x += v.x; s.y += v.y; s.z += v.z; s.w += v.w;
                    }
                    ((float4*)(Xb + node * XS_NODE + 10 * 128))[16 + c4] =
                        make_float4(s.x * 0.1f, s.y * 0.1f, s.z * 0.1f, s.w * 0.1f);
                }
            }
            mbar_arrive(mb + slot * 16);            // full
            if (++slot == NSLOT) { slot = 0; ph ^= 1; }
        }
    } else {
        // ===================== CONSUMER (2 cols/thread) =====================
        const int node = t >> 6;
        const int col  = t & 63;
        const ulonglong2* wpa = (const ulonglong2*)(w0Ts + col * W0T_LD);
        const ulonglong2* wpb = (const ulonglong2*)(w0Ts + (col + 64) * W0T_LD);
        const float bbA = b0s[col];
        const float bbB = b0s[col + 64];

        int slot = 0, ph = 0;
        for (int np = blockIdx.x * 2; np < N_NODES; np += gridDim.x * 2) {
            mbar_wait(mb + slot * 16, ph);          // full
            const float* X = ring + slot * XS_PAIR + node * XS_NODE;

            ull accA[11], accB[11];
            #pragma unroll
            for (int r = 0; r < 11; ++r) { accA[r] = 0ull; accB[r] = 0ull; }

            #pragma unroll 2
            for (int kq = 0; kq < 32; ++kq) {
                const ulonglong2 wa = wpa[kq];
                const ulonglong2 wb = wpb[kq];
                #pragma unroll
                for (int r = 0; r < 11; ++r) {
                    const ulonglong2 x = *(const ulonglong2*)(X + r * 128 + kq * 4);
                    ffma2(accA[r], x.x, wa.x);
                    ffma2(accA[r], x.y, wa.y);
                    ffma2(accB[r], x.x, wb.x);
                    ffma2(accB[r], x.y, wb.y);
                }
            }

            float ymA = 0.f, ymB = 0.f;
            #pragma unroll
            for (int r = 0; r < KK1; ++r) {
                ymA += fmaxf(f2sum(accA[r]) + bbA, 0.f);
                ymB += fmaxf(f2sum(accB[r]) + bbB, 0.f);
            }
            const float a01A = fmaxf(f2sum(accA[10]) + bbA, 0.f);
            const float a01B = fmaxf(f2sum(accB[10]) + bbB, 0.f);

            float* xr = g_XR + (np + node) * 256;
            xr[col]            = a01A;
            xr[col + 64]       = a01B;
            xr[128 + col]      = ymA * 0.1f;
            xr[128 + col + 64] = ymB * 0.1f;

            mbar_arrive(mb + slot * 16 + 8);        // empty
            if (++slot == NSLOT) { slot = 0; ph ^= 1; }
        }
    }
}

// ---------------------------------------------------------------------------
// Kernel B (v3): 16 rows/thread weight amortization.
// 512 thr = 4 row-groups x 128 cols; 64-row XR tile staged in smem.
// Per kq per thread: 1 weight LDS.128 + 16 x-broadcasts for 32 FFMA2
// -> FMA-bound. Run-length coalesced atomics over sorted gids.
// ---------------------------------------------------------------------------
#define W1T_LD 260
#define KB_ROWS 64
extern "C" __global__ void __launch_bounds__(512, 1)
kB(const float* __restrict__ w1, const float* __restrict__ b1,
   const int* __restrict__ gid)
{
    extern __shared__ float sm[];
    float* w1Ts = sm;                       // [128][260] = 33280 floats
    float* xs   = sm + 33280;               // 64 rows x 256 = 16384 floats
    int*   sgid = (int*)(sm + 33280 + 16384);  // 64 ints

    const int t = threadIdx.x;

    // Stage w1 transposed: w1Ts[c][k] = w1[k][c];  w1 is [256][128].
    for (int i = t; i < 8192; i += 512) {
        const int k  = i >> 5;
        const int cq = i & 31;
        const float4 v = __ldg((const float4*)(w1 + k * 128) + cq);
        w1Ts[(cq * 4 + 0) * W1T_LD + k] = v.x;
        w1Ts[(cq * 4 + 1) * W1T_LD + k] = v.y;
        w1Ts[(cq * 4 + 2) * W1T_LD + k] = v.z;
        w1Ts[(cq * 4 + 3) * W1T_LD + k] = v.w;
    }

    const int c  = t & 127;                 // output column
    const int rg = t >> 7;                  // row-group 0..3 (warp-uniform)
    const float bb = __ldg(b1 + c);
    const ulonglong2* wp = (const ulonglong2*)(w1Ts + c * W1T_LD);

    for (int rbase = blockIdx.x * KB_ROWS; rbase < N_NODES;
         rbase += gridDim.x * KB_ROWS) {
        const int nrows = min(KB_ROWS, N_NODES - rbase);

        __syncthreads();   // xs reusable (also covers w1Ts on first pass)
        for (int i = t; i < KB_ROWS * 64; i += 512) {
            const int row = i >> 6, q = i & 63;
            ((float4*)(xs + row * 256))[q] = (row < nrows)
                ? __ldg((const float4*)(g_XR + (rbase + row) * 256) + q)
                : make_float4(0.f, 0.f, 0.f, 0.f);
        }
        if (t < KB_ROWS) sgid[t] = (t < nrows) ? __ldg(gid + rbase + t) : -1;
        __syncthreads();

        // 16 rows x 1 col per thread
        ull acc[16];
        #pragma unroll
        for (int r = 0; r < 16; ++r) acc[r] = 0ull;

        const float* xb = xs + (rg * 16) * 256;
        #pragma unroll 2
        for (int kq = 0; kq < 64; ++kq) {
            const ulonglong2 w = wp[kq];
            #pragma unroll
            for (int r = 0; r < 16; ++r) {
                const ulonglong2 x = *(const ulonglong2*)(xb + r * 256 + kq * 4);
                ffma2(acc[r], x.x, w.x);
                ffma2(acc[r], x.y, w.y);
            }
        }

        // relu + run-length coalesced segment atomics (gids sorted)
        int curg = sgid[rg * 16];
        float s = 0.f;
        #pragma unroll
        for (int r = 0; r < 16; ++r) {
            const int row = rg * 16 + r;
            if (row < nrows) {
                const float y = fmaxf(f2sum(acc[r]) + bb, 0.f);
                const int g = sgid[row];
                if (g != curg) {
                    if (curg >= 0) atomicAdd(&g_Seg[curg * OUTD + c], s);
                    s = 0.f; curg = g;
                }
                s += y;
            }
        }
        if (curg >= 0) atomicAdd(&g_Seg[curg * OUTD + c], s);
    }
}

// ---------------------------------------------------------------------------
// Kernel C: readout MLP, one block per graph.
// ---------------------------------------------------------------------------
extern "C" __global__ void __launch_bounds__(64, 8)
kC(const float* __restrict__ wr1, const float* __restrict__ br1,
   const float* __restrict__ wr2, const float* __restrict__ br2,
   const float* __restrict__ wr3, const float* __restrict__ br3,
   float* __restrict__ out)
{
    __shared__ float r1s[35];
    __shared__ float r2s[35];
    const int g = blockIdx.x, t = threadIdx.x;
    const float SC = 1.0507009873554805f;
    const float AL = 1.6732632423543772f;

    if (t < 35) {
        float acc = br1[t];
        #pragma unroll 4
        for (int k = 0; k < OUTD; ++k)
            acc = fmaf(g_Seg[g * OUTD + k], wr1[k * 35 + t], acc);
        r1s[t] = (acc > 0.f) ? SC * acc : SC * AL * (expf(acc) - 1.f);
    }
    __syncthreads();

    if (t < 35) {
        float acc = br2[t];
        #pragma unroll
        for (int k = 0; k < 35; ++k)
            acc = fmaf(r1s[k], wr2[k * 35 + t], acc);
        r2s[t] = (acc > 0.f) ? SC * acc : SC * AL * (expf(acc) - 1.f);
    }
    __syncthreads();

    if (t == 0) {
        float acc = br3[0];
        #pragma unroll
        for (int k = 0; k < 35; ++k)
            acc = fmaf(r2s[k], wr3[k], acc);
        out[g] = acc;
    }
}

// ---------------------------------------------------------------------------
extern "C" void kernel_launch(void* const* d_in, const int* in_sizes, int n_in,
                              void* d_out, int out_size)
{
    const float* h0  = (const float*)d_in[0];
    const float* h1  = (const float*)d_in[1];
    const float* h2  = (const float*)d_in[2];
    const float* w0  = (const float*)d_in[3];
    const float* b0  = (const float*)d_in[4];
    const float* w1  = (const float*)d_in[5];
    const float* b1  = (const float*)d_in[6];
    const float* wr1 = (const float*)d_in[7];
    const float* br1 = (const float*)d_in[8];
    const float* wr2 = (const float*)d_in[9];
    const float* br2 = (const float*)d_in[10];
    const float* wr3 = (const float*)d_in[11];
    const float* br3 = (const float*)d_in[12];
    const int*   gid = (const int*)d_in[13];

    const int smA = (8 + 16896 + 128 + NSLOT * XS_PAIR) * 4;    // 113,184 B
    const int smB = (33280 + 16384 + 64) * 4;                   // 198,912 B
    cudaFuncSetAttribute(kA, cudaFuncAttributeMaxDynamicSharedMemorySize, smA);
    cudaFuncSetAttribute(kB, cudaFuncAttributeMaxDynamicSharedMemorySize, smB);

    kA<<<148, 384, smA>>>(h0, h1, h2, w0, b0);
    kB<<<148, 512, smB>>>(w1, b1, gid);
    kC<<<NGRAPH, 64>>>(wr1, br1, wr2, br2, wr3, br3, (float*)d_out);
}